// round 6
// baseline (speedup 1.0000x reference)
#include <cuda_runtime.h>

#define T_LEN   1000
#define NB      4
#define GRIDB   128
#define THREADS 768

typedef unsigned long long ull;

__device__ float g_xg[512 * T_LEN * 256];   // precomputed input projections (+biases)

__device__ __forceinline__ ull fma2(ull a, ull b, ull c) {
    ull d;
    asm("fma.rn.f32x2 %0, %1, %2, %3;" : "=l"(d) : "l"(a), "l"(b), "l"(c));
    return d;
}
__device__ __forceinline__ ull pack2(float lo, float hi) {
    ull d;
    asm("mov.b64 %0, {%1, %2};" : "=l"(d) : "f"(lo), "f"(hi));
    return d;
}
__device__ __forceinline__ float hadd(ull a) {
    float lo, hi;
    asm("mov.b64 {%0, %1}, %2;" : "=f"(lo), "=f"(hi) : "l"(a));
    return lo + hi;
}
__device__ __forceinline__ float tanhap(float x) {
    float y;
    asm("tanh.approx.f32 %0, %1;" : "=f"(y) : "f"(x));
    return y;
}

// ---------------- pass 1: xg[b][t][j] = b_ih1[j]+b_hh1[j] + sum_k w_ih1[j][k]*x[b][k][t]
extern "C" __global__ void __launch_bounds__(256)
xg_kernel(const float* __restrict__ x, const float* __restrict__ w_ih1,
          const float* __restrict__ b_ih1, const float* __restrict__ b_hh1)
{
    __shared__ float xt[26 * 100];
    const int tt = blockIdx.x;          // t-tile (0..9), 100 steps each
    const int b  = blockIdx.y;          // batch
    const int j  = threadIdx.x;         // gate row 0..255
    const int t0 = tt * 100;

    const float* xb = x + (size_t)b * 26 * T_LEN;
    for (int idx = j; idx < 26 * 100; idx += 256) {
        const int k = idx / 100, i = idx - k * 100;
        xt[idx] = xb[k * T_LEN + t0 + i];
    }
    float w[26];
    #pragma unroll
    for (int k = 0; k < 26; ++k) w[k] = w_ih1[j * 26 + k];
    const float bias = b_ih1[j] + b_hh1[j];
    __syncthreads();

    float* og = g_xg + ((size_t)b * T_LEN + t0) * 256 + j;
    #pragma unroll 4
    for (int i = 0; i < 100; ++i) {
        float a = bias;
        #pragma unroll
        for (int k = 0; k < 26; ++k) a = fmaf(w[k], xt[k * 100 + i], a);
        og[(size_t)i * 256] = a;
    }
}

// ---------------- pass 2: persistent recurrent kernel, fused update, 1 barrier/step ----
// lane bits: b4 = khalf, b3:b2 = gate, b1:b0 = n_loc
// tid 0..511  : LSTM1 warp w (0..15) -> n = w*4+n_loc (0..63), row = gate*64+n
// tid 512..767: LSTM2 warp w (0..7)  -> n = w*4+n_loc (0..31), row = gate*32+n
extern "C" __global__ void __launch_bounds__(THREADS, 1)
lstm_kernel(const float* __restrict__ w_hh1,
            const float* __restrict__ w_ih2, const float* __restrict__ w_hh2,
            const float* __restrict__ b_ih2, const float* __restrict__ b_hh2,
            const float* __restrict__ w_fc1, const float* __restrict__ b_fc1,
            const float* __restrict__ w_fc2, const float* __restrict__ b_fc2,
            float* __restrict__ out)
{
    __shared__ __align__(16) float v1s[2][NB * 64];   // h1 ping-pong
    __shared__ __align__(16) float v2s[2][NB * 96];   // [h1(64)|h2(32)] ping-pong
    __shared__ float fcs[64];

    const int tid  = threadIdx.x;
    const int b0   = blockIdx.x * NB;
    const int lane = tid & 31;
    const bool is1 = tid < 512;
    const int kh   = (lane >> 4) & 1;
    const int gate = (lane >> 2) & 3;
    const int nloc = lane & 3;
    const int bl   = lane & 0x13;                     // lane with gate bits cleared

    const int n1 = (tid >> 5) * 4 + nloc;             // 0..63  (is1)
    const int r1 = gate * 64 + n1;                    // 0..255
    const int n2 = ((tid - 512) >> 5) * 4 + nloc;     // 0..31  (!is1)
    const int r2 = gate * 32 + n2;                    // 0..127

    // ----- per-thread weights (packed f32x2) -----
    ull W[24];
    float bias2 = 0.f;
    if (is1) {
        const float* wr = w_hh1 + r1 * 64 + kh * 32;
        #pragma unroll
        for (int i = 0; i < 16; ++i) W[i] = pack2(wr[2 * i], wr[2 * i + 1]);
    } else {
        float wt[48];
        #pragma unroll
        for (int k = 0; k < 48; ++k) {
            const int kk = kh * 48 + k;
            wt[k] = (kk < 64) ? w_ih2[r2 * 64 + kk] : w_hh2[r2 * 32 + (kk - 64)];
        }
        #pragma unroll
        for (int i = 0; i < 24; ++i) W[i] = pack2(wt[2 * i], wt[2 * i + 1]);
        bias2 = b_ih2[r2] + b_hh2[r2];
    }

    for (int e = tid; e < 2 * NB * 64; e += THREADS) ((float*)v1s)[e] = 0.f;
    for (int e = tid; e < 2 * NB * 96; e += THREADS) ((float*)v2s)[e] = 0.f;

    const bool stl = (lane & 0x1C) == 0;              // gate==0 && khalf==0 lanes store
    const float* xgp = g_xg + (size_t)b0 * T_LEN * 256 + r1;
    const size_t BS = (size_t)T_LEN * 256;
    float xr[4] = {0.f, 0.f, 0.f, 0.f};
    if (is1) {
        #pragma unroll
        for (int b = 0; b < 4; ++b) xr[b] = xgp[b * BS];
    }

    float c[4] = {0.f, 0.f, 0.f, 0.f};
    __syncthreads();

    #pragma unroll 1
    for (int t = 0; t <= T_LEN; ++t) {
        const int cur = t & 1, nxt = cur ^ 1;
        if (is1) {
            if (t < T_LEN) {
                // prefetch xg(t+1)
                float nx[4];
                const int tp = (t + 1 < T_LEN) ? t + 1 : 0;
                #pragma unroll
                for (int b = 0; b < 4; ++b) nx[b] = xgp[(size_t)tp * 256 + b * BS];

                const float* vb = v1s[cur] + kh * 32;
                ull a0 = 0, a1 = 0, a2 = 0, a3 = 0;
                #pragma unroll
                for (int q = 0; q < 8; ++q) {
                    ulonglong2 v;
                    v = *(const ulonglong2*)(vb + 0 * 64 + q * 4);
                    a0 = fma2(W[2 * q], v.x, a0); a0 = fma2(W[2 * q + 1], v.y, a0);
                    v = *(const ulonglong2*)(vb + 1 * 64 + q * 4);
                    a1 = fma2(W[2 * q], v.x, a1); a1 = fma2(W[2 * q + 1], v.y, a1);
                    v = *(const ulonglong2*)(vb + 2 * 64 + q * 4);
                    a2 = fma2(W[2 * q], v.x, a2); a2 = fma2(W[2 * q + 1], v.y, a2);
                    v = *(const ulonglong2*)(vb + 3 * 64 + q * 4);
                    a3 = fma2(W[2 * q], v.x, a3); a3 = fma2(W[2 * q + 1], v.y, a3);
                }
                float p[4] = {hadd(a0), hadd(a1), hadd(a2), hadd(a3)};
                #pragma unroll
                for (int b = 0; b < 4; ++b) {
                    p[b] += __shfl_xor_sync(0xffffffffu, p[b], 16);
                    p[b] += xr[b];
                    // activation: sigmoid for gates 0,1,3; tanh for gate 2
                    const float th = tanhap(gate == 2 ? p[b] : 0.5f * p[b]);
                    const float val = (gate == 2) ? th : fmaf(0.5f, th, 0.5f);
                    const float gi = __shfl_sync(0xffffffffu, val, bl);
                    const float gf = __shfl_sync(0xffffffffu, val, bl | 4);
                    const float gg = __shfl_sync(0xffffffffu, val, bl | 8);
                    const float go = __shfl_sync(0xffffffffu, val, bl | 12);
                    c[b] = gf * c[b] + gi * gg;
                    const float h = go * tanhap(c[b]);
                    if (stl) {
                        v1s[nxt][b * 64 + n1] = h;
                        v2s[nxt][b * 96 + n1] = h;
                    }
                    xr[b] = nx[b];
                }
            }
        } else if (t > 0) {
            const float* vb = v2s[cur] + kh * 48;
            ull a0 = 0, a1 = 0, a2 = 0, a3 = 0;
            #pragma unroll
            for (int q = 0; q < 12; ++q) {
                ulonglong2 v;
                v = *(const ulonglong2*)(vb + 0 * 96 + q * 4);
                a0 = fma2(W[2 * q], v.x, a0); a0 = fma2(W[2 * q + 1], v.y, a0);
                v = *(const ulonglong2*)(vb + 1 * 96 + q * 4);
                a1 = fma2(W[2 * q], v.x, a1); a1 = fma2(W[2 * q + 1], v.y, a1);
                v = *(const ulonglong2*)(vb + 2 * 96 + q * 4);
                a2 = fma2(W[2 * q], v.x, a2); a2 = fma2(W[2 * q + 1], v.y, a2);
                v = *(const ulonglong2*)(vb + 3 * 96 + q * 4);
                a3 = fma2(W[2 * q], v.x, a3); a3 = fma2(W[2 * q + 1], v.y, a3);
            }
            float p[4] = {hadd(a0), hadd(a1), hadd(a2), hadd(a3)};
            #pragma unroll
            for (int b = 0; b < 4; ++b) {
                p[b] += __shfl_xor_sync(0xffffffffu, p[b], 16);
                p[b] += bias2;
                const float th = tanhap(gate == 2 ? p[b] : 0.5f * p[b]);
                const float val = (gate == 2) ? th : fmaf(0.5f, th, 0.5f);
                const float gi = __shfl_sync(0xffffffffu, val, bl);
                const float gf = __shfl_sync(0xffffffffu, val, bl | 4);
                const float gg = __shfl_sync(0xffffffffu, val, bl | 8);
                const float go = __shfl_sync(0xffffffffu, val, bl | 12);
                c[b] = gf * c[b] + gi * gg;
                const float h = go * tanhap(c[b]);
                if (stl) v2s[nxt][b * 96 + 64 + n2] = h;
            }
        }
        __syncthreads();     // nxt buffer complete; cur reusable
    }

    // ----- FC head on final h2 = v2s[1][b][64..95]  (nxt of t=1000 is buffer 1) -----
    if (tid < 64) {
        const int b = tid >> 4, f = tid & 15;
        float a = __ldg(b_fc1 + f);
        #pragma unroll
        for (int k = 0; k < 32; ++k)
            a += __ldg(w_fc1 + f * 32 + k) * v2s[1][b * 96 + 64 + k];
        fcs[b * 16 + f] = fmaxf(a, 0.f);
    }
    __syncthreads();
    if (tid < 40) {
        const int b = tid / 10, o = tid - b * 10;
        float a = __ldg(b_fc2 + o);
        #pragma unroll
        for (int k = 0; k < 16; ++k)
            a += __ldg(w_fc2 + o * 16 + k) * fcs[b * 16 + k];
        out[(b0 + b) * 10 + o] = a;
    }
}

extern "C" void kernel_launch(void* const* d_in, const int* in_sizes, int n_in,
                              void* d_out, int out_size) {
    (void)in_sizes; (void)n_in; (void)out_size;
    xg_kernel<<<dim3(10, 512), 256>>>(
        (const float*)d_in[0],   // x
        (const float*)d_in[1],   // w_ih1
        (const float*)d_in[3],   // b_ih1
        (const float*)d_in[4]);  // b_hh1
    lstm_kernel<<<GRIDB, THREADS>>>(
        (const float*)d_in[2],   // w_hh1
        (const float*)d_in[5],   // w_ih2
        (const float*)d_in[6],   // w_hh2
        (const float*)d_in[7],   // b_ih2
        (const float*)d_in[8],   // b_hh2
        (const float*)d_in[9],   // w_fc1
        (const float*)d_in[10],  // b_fc1
        (const float*)d_in[11],  // w_fc2
        (const float*)d_in[12],  // b_fc2
        (float*)d_out);
}